// round 14
// baseline (speedup 1.0000x reference)
#include <cuda_runtime.h>
#include <cstdint>

// PWC-Net correlation, B=8, C=128, H=112, W=192, 81 disps (dy,dx in [-4,4]).
// Round 14: NO pad buffer / pad kernel. corr reads `second` directly with
// three aligned LDG.128 (cols w0-4 / w0 / w0+4). Edge handling:
//  - w edges (quads 0,47): clamp that one load's column; all contaminated
//    outputs are boundary-zeros, fixed by epilogue masks.
//  - h edges (y OOB): V pointers -> static zero quad with stride 0.

#define B_ 8
#define C_ 128
#define H_ 112
#define W_ 192
#define HW_ (H_ * W_)

typedef unsigned long long ull;

__device__ __align__(16) float4 g_zero[4];   // zero-initialized

__device__ __forceinline__ void fma2(ull& acc, ull a, ull b) {
    asm("fma.rn.f32x2 %0, %1, %2, %0;" : "+l"(acc) : "l"(a), "l"(b));
}
__device__ __forceinline__ void mul2(ull& v, ull s) {
    asm("mul.rn.f32x2 %0, %0, %1;" : "+l"(v) : "l"(s));
}
__device__ __forceinline__ ull pack_hl(ull a, ull b) {   // (a.hi, b.lo)
    return (a >> 32) | (b << 32);
}
__device__ __forceinline__ ull swap2(ull a) {            // (a.hi, a.lo)
    return (a >> 32) | (a << 32);
}
__device__ __forceinline__ ull lo_(float x, float y) {
    return (ull)__float_as_uint(x) | ((ull)__float_as_uint(y) << 32);
}

// zero the output elements whose true value is boundary-zero (w + dx - 4
// outside [0, 192)). pk = 4 pixels (w0..w0+3) of displacement channel dx.
__device__ __forceinline__ void fix_edges(ulonglong2& pk, int dx, int w0) {
    if (w0 == 0) {
        if      (dx == 0) { pk.x = 0; pk.y = 0; }
        else if (dx == 1) { pk.x = 0; pk.y &= 0xFFFFFFFF00000000ULL; }
        else if (dx == 2) { pk.x = 0; }
        else if (dx == 3) { pk.x &= 0xFFFFFFFF00000000ULL; }
    } else if (w0 == 188) {
        if      (dx == 5) { pk.y &= 0x00000000FFFFFFFFULL; }
        else if (dx == 6) { pk.y = 0; }
        else if (dx == 7) { pk.y = 0; pk.x &= 0x00000000FFFFFFFFULL; }
        else if (dx == 8) { pk.x = 0; pk.y = 0; }
    }
}

__global__ __launch_bounds__(240, 2)
void corr81_kernel(const float* __restrict__ first,
                   const float* __restrict__ second,
                   float* __restrict__ out) {
    const int h0  = 2 * blockIdx.x;    // output rows h0, h0+1
    const int wh  = blockIdx.y;        // W half: 0 or 1
    const int b   = blockIdx.z;
    const int tid = threadIdx.x;       // 0..239
    const int pq  = tid % 24;
    const int g   = tid / 24;          // 0..9: second row = h0 + g - 4
    const int w0  = 4 * (24 * wh + pq);

    ull e0[5], a0[5], f0e[5], f0a[5];
    ull e1[5], a1[5], f1e[5], f1a[5];
#pragma unroll
    for (int m = 0; m < 5; m++) {
        e0[m]=0; a0[m]=0; f0e[m]=0; f0a[m]=0;
        e1[m]=0; a1[m]=0; f1e[m]=0; f1a[m]=0;
    }

    // V pointers: three aligned quads at cols w0-4 / w0 / w0+4 of row y.
    const int y   = h0 + g - 4;
    const bool yok = (y >= 0 && y < H_);
    const int yc  = y < 0 ? 0 : (y >= H_ ? H_ - 1 : y);
    const int c0  = (w0 >= 4)   ? (w0 - 4) : 0;     // clamped (quad 0)
    const int c2  = (w0 <= 184) ? (w0 + 4) : 184;   // clamped (quad 47)

    const float4* rowb = reinterpret_cast<const float4*>(
        second + ((size_t)(b * C_) * H_ + yc) * W_);
    const float4* p0;
    const float4* p1;
    const float4* p2;
    size_t incv;
    if (yok) {
        p0 = rowb + (c0 >> 2);
        p1 = rowb + (w0 >> 2);
        p2 = rowb + (c2 >> 2);
        incv = HW_ / 4;
    } else {
        p0 = g_zero; p1 = g_zero; p2 = g_zero;
        incv = 0;
    }

    const float4* fp0 = reinterpret_cast<const float4*>(
        first + ((size_t)(b * C_) * H_ + h0) * W_ + w0);
    const float4* fp1 = fp0 + W_ / 4;

    // prologue: V for channel 0
    float4 V0 = *p0, V1 = *p1, V2 = *p2;

    for (int c = 0; c < C_; c++) {
        // distance-1 prefetch of channel c+1's V (stride 0 on last iter)
        const size_t adv = (c < C_ - 1) ? incv : 0;
        const float4* p0n = p0 + adv;
        const float4* p1n = p1 + adv;
        const float4* p2n = p2 + adv;
        const float4 nV0 = *p0n;
        const float4 nV1 = *p1n;
        const float4 nV2 = *p2n;

        const float4 F0 = *fp0;
        const float4 F1 = *fp1;
        fp0 += HW_ / 4;
        fp1 += HW_ / 4;

        const ull E0 = lo_(V0.x, V0.y);
        const ull E1 = lo_(V0.z, V0.w);
        const ull E2 = lo_(V1.x, V1.y);
        const ull E3 = lo_(V1.z, V1.w);
        const ull E4 = lo_(V2.x, V2.y);
        const ull E5 = lo_(V2.z, V2.w);

        const ull p0a = lo_(F0.x, F0.y), p0b = lo_(F0.z, F0.w);
        const ull s0a = swap2(p0a),      s0b = swap2(p0b);
        const ull p1a = lo_(F1.x, F1.y), p1b = lo_(F1.z, F1.w);
        const ull s1a = swap2(p1a),      s1b = swap2(p1b);

        // h0: pair a uses E0..E4, pair b uses E1..E5
        fma2(e0[0], p0a, E0);  fma2(a0[0], s0a, E0);
        fma2(e0[1], p0a, E1);  fma2(a0[1], s0a, E1);
        fma2(e0[2], p0a, E2);  fma2(a0[2], s0a, E2);
        fma2(e0[3], p0a, E3);  fma2(a0[3], s0a, E3);
        fma2(e0[4], p0a, E4);  fma2(a0[4], s0a, E4);
        fma2(f0e[0], p0b, E1); fma2(f0a[0], s0b, E1);
        fma2(f0e[1], p0b, E2); fma2(f0a[1], s0b, E2);
        fma2(f0e[2], p0b, E3); fma2(f0a[2], s0b, E3);
        fma2(f0e[3], p0b, E4); fma2(f0a[3], s0b, E4);
        fma2(f0e[4], p0b, E5); fma2(f0a[4], s0b, E5);

        // h1: same E operands
        fma2(e1[0], p1a, E0);  fma2(a1[0], s1a, E0);
        fma2(e1[1], p1a, E1);  fma2(a1[1], s1a, E1);
        fma2(e1[2], p1a, E2);  fma2(a1[2], s1a, E2);
        fma2(e1[3], p1a, E3);  fma2(a1[3], s1a, E3);
        fma2(e1[4], p1a, E4);  fma2(a1[4], s1a, E4);
        fma2(f1e[0], p1b, E1); fma2(f1a[0], s1b, E1);
        fma2(f1e[1], p1b, E2); fma2(f1a[1], s1b, E2);
        fma2(f1e[2], p1b, E3); fma2(f1a[2], s1b, E3);
        fma2(f1e[3], p1b, E4); fma2(f1a[3], s1b, E4);
        fma2(f1e[4], p1b, E5); fma2(f1a[4], s1b, E5);

        V0 = nV0; V1 = nV1; V2 = nV2;
        p0 = p0n; p1 = p1n; p2 = p2n;
    }

    const unsigned sb = __float_as_uint(1.0f / (float)C_);
    const ull scale2 = (ull)sb | ((ull)sb << 32);

    if (g <= 8) {   // set 0: channel g*9+dx at row h0
        float* od = out + (((size_t)(b * 81 + g * 9)) * H_ + h0) * W_ + w0;
#pragma unroll
        for (int m = 0; m < 5; m++) {
            ull va = e0[m];  mul2(va, scale2);
            ull vb = f0e[m]; mul2(vb, scale2);
            ulonglong2 pk; pk.x = va; pk.y = vb;
            fix_edges(pk, 2 * m, w0);
            *reinterpret_cast<ulonglong2*>(od + (size_t)(2 * m) * HW_) = pk;
        }
#pragma unroll
        for (int m = 0; m < 4; m++) {
            ull va = pack_hl(a0[m], a0[m + 1]); mul2(va, scale2);
            ull vb = pack_hl(f0a[m], f0a[m + 1]); mul2(vb, scale2);
            ulonglong2 pk; pk.x = va; pk.y = vb;
            fix_edges(pk, 2 * m + 1, w0);
            *reinterpret_cast<ulonglong2*>(od + (size_t)(2 * m + 1) * HW_) = pk;
        }
    }
    if (g >= 1) {   // set 1: channel (g-1)*9+dx at row h0+1
        float* od = out + (((size_t)(b * 81 + (g - 1) * 9)) * H_ + (h0 + 1)) * W_ + w0;
#pragma unroll
        for (int m = 0; m < 5; m++) {
            ull va = e1[m];  mul2(va, scale2);
            ull vb = f1e[m]; mul2(vb, scale2);
            ulonglong2 pk; pk.x = va; pk.y = vb;
            fix_edges(pk, 2 * m, w0);
            *reinterpret_cast<ulonglong2*>(od + (size_t)(2 * m) * HW_) = pk;
        }
#pragma unroll
        for (int m = 0; m < 4; m++) {
            ull va = pack_hl(a1[m], a1[m + 1]); mul2(va, scale2);
            ull vb = pack_hl(f1a[m], f1a[m + 1]); mul2(vb, scale2);
            ulonglong2 pk; pk.x = va; pk.y = vb;
            fix_edges(pk, 2 * m + 1, w0);
            *reinterpret_cast<ulonglong2*>(od + (size_t)(2 * m + 1) * HW_) = pk;
        }
    }
}

extern "C" void kernel_launch(void* const* d_in, const int* in_sizes, int n_in,
                              void* d_out, int out_size) {
    const float* first  = (const float*)d_in[0];
    const float* second = (const float*)d_in[1];
    float* out = (float*)d_out;

    dim3 grid(H_ / 2, 2, B_);   // (56 h-pairs, 2 W-halves, 8 batches)
    corr81_kernel<<<grid, 240>>>(first, second, out);
}

// round 15
// speedup vs baseline: 1.1128x; 1.1128x over previous
#include <cuda_runtime.h>
#include <cstdint>

// PWC-Net correlation, B=8, C=128, H=112, W=192, 81 disps (dy,dx in [-4,4]).
// Round 15: R13 (h-pair register blocking, 240-thr blocks, distance-1 register
// V pipeline) + distance-4 prefetch.global.L2 on both streams. L2 prefetch
// needs no destination registers, so it deepens the pipeline without touching
// the 128-reg schedule. g_spad gains a 4-channel margin; `first` prefetches
// are clamped in-range with a select.

#define B_ 8
#define C_ 128
#define H_ 112
#define W_ 192
#define HW_ (H_ * W_)
#define HP_ 120     // H + 8
#define WP_ 208     // 4 left pad + 192 + 12 right pad (floats)
#define HWP_ (HP_ * WP_)

typedef unsigned long long ull;

// padded second [B,C,HP,WP] + 4-channel prefetch margin (never consumed)
__device__ __align__(16) float g_spad[(B_ * C_ + 4) * HWP_];

__device__ __forceinline__ void fma2(ull& acc, ull a, ull b) {
    asm("fma.rn.f32x2 %0, %1, %2, %0;" : "+l"(acc) : "l"(a), "l"(b));
}
__device__ __forceinline__ void mul2(ull& v, ull s) {
    asm("mul.rn.f32x2 %0, %0, %1;" : "+l"(v) : "l"(s));
}
__device__ __forceinline__ ull pack_hl(ull a, ull b) {   // (a.hi, b.lo)
    return (a >> 32) | (b << 32);
}
__device__ __forceinline__ ull swap2(ull a) {            // (a.hi, a.lo)
    return (a >> 32) | (a << 32);
}
__device__ __forceinline__ ull lo_(float x, float y) {
    return (ull)__float_as_uint(x) | ((ull)__float_as_uint(y) << 32);
}
__device__ __forceinline__ void pfl2(const void* p) {
    asm volatile("prefetch.global.L2 [%0];" :: "l"(p));
}

__global__ __launch_bounds__(256)
void pad_kernel(const float* __restrict__ second) {
    int i = blockIdx.x * blockDim.x + threadIdx.x;
    const int total = B_ * C_ * HP_ * (WP_ / 4);
    if (i >= total) return;
    int q    = i % (WP_ / 4);            // 0..51
    int rest = i / (WP_ / 4);
    int y    = rest % HP_;
    int bc   = rest / HP_;
    int ys   = y - 4;
    float4 v = make_float4(0.f, 0.f, 0.f, 0.f);
    if (q >= 1 && q <= 48 && ys >= 0 && ys < H_) {
        v = *reinterpret_cast<const float4*>(
            second + ((size_t)bc * H_ + ys) * W_ + (4 * q - 4));
    }
    reinterpret_cast<float4*>(g_spad)[i] = v;
}

__global__ __launch_bounds__(240, 2)
void corr81_kernel(const float* __restrict__ first,
                   float* __restrict__ out) {
    const int h0  = 2 * blockIdx.x;    // output rows h0, h0+1
    const int wh  = blockIdx.y;        // W half: 0 or 1
    const int b   = blockIdx.z;
    const int tid = threadIdx.x;       // 0..239
    const int pq  = tid % 24;          // quad within half
    const int g   = tid / 24;          // 0..9: second padded row = h0 + g
    const int w0  = 4 * (24 * wh + pq);

    // set 0: output row h0, dy_pad = g      (store if g<=8)
    // set 1: output row h0+1, dy_pad = g-1  (store if g>=1)
    ull e0[5], a0[5], f0e[5], f0a[5];
    ull e1[5], a1[5], f1e[5], f1a[5];
#pragma unroll
    for (int m = 0; m < 5; m++) {
        e0[m]=0; a0[m]=0; f0e[m]=0; f0a[m]=0;
        e1[m]=0; a1[m]=0; f1e[m]=0; f1a[m]=0;
    }

    const float4* sp = reinterpret_cast<const float4*>(
        g_spad + ((size_t)(b * C_) * HP_ + (h0 + g)) * WP_ + w0);
    const float4* fp0 = reinterpret_cast<const float4*>(
        first + ((size_t)(b * C_) * H_ + h0) * W_ + w0);
    const float4* fp1 = fp0 + W_ / 4;

    // prologue: V for channel 0
    float4 V0 = sp[0], V1 = sp[1], V2 = sp[2];

    for (int c = 0; c < C_; c++) {
        // distance-1 register prefetch of channel c+1's V
        const int adv = (c < C_ - 1) ? 1 : 0;
        const float4* spn = sp + (size_t)adv * (HWP_ / 4);
        const float4 nV0 = spn[0];
        const float4 nV1 = spn[1];
        const float4 nV2 = spn[2];

        const float4 F0 = *fp0;
        const float4 F1 = *fp1;

        // distance-4 L2 prefetch (no registers, immediate offsets)
        pfl2(sp + 4 * (HWP_ / 4));          // V span left
        pfl2(sp + 4 * (HWP_ / 4) + 2);      // V span right
        const size_t fadv = (c <= C_ - 5) ? (size_t)(4 * (HW_ / 4)) : 0;
        pfl2(fp0 + fadv);                   // F row h0
        pfl2(fp1 + fadv);                   // F row h0+1

        fp0 += HW_ / 4;
        fp1 += HW_ / 4;

        const ull E0 = lo_(V0.x, V0.y);
        const ull E1 = lo_(V0.z, V0.w);
        const ull E2 = lo_(V1.x, V1.y);
        const ull E3 = lo_(V1.z, V1.w);
        const ull E4 = lo_(V2.x, V2.y);
        const ull E5 = lo_(V2.z, V2.w);

        const ull p0a = lo_(F0.x, F0.y), p0b = lo_(F0.z, F0.w);
        const ull s0a = swap2(p0a),      s0b = swap2(p0b);
        const ull p1a = lo_(F1.x, F1.y), p1b = lo_(F1.z, F1.w);
        const ull s1a = swap2(p1a),      s1b = swap2(p1b);

        // h0: pair a uses E0..E4, pair b uses E1..E5
        fma2(e0[0], p0a, E0);  fma2(a0[0], s0a, E0);
        fma2(e0[1], p0a, E1);  fma2(a0[1], s0a, E1);
        fma2(e0[2], p0a, E2);  fma2(a0[2], s0a, E2);
        fma2(e0[3], p0a, E3);  fma2(a0[3], s0a, E3);
        fma2(e0[4], p0a, E4);  fma2(a0[4], s0a, E4);
        fma2(f0e[0], p0b, E1); fma2(f0a[0], s0b, E1);
        fma2(f0e[1], p0b, E2); fma2(f0a[1], s0b, E2);
        fma2(f0e[2], p0b, E3); fma2(f0a[2], s0b, E3);
        fma2(f0e[3], p0b, E4); fma2(f0a[3], s0b, E4);
        fma2(f0e[4], p0b, E5); fma2(f0a[4], s0b, E5);

        // h1: same E operands
        fma2(e1[0], p1a, E0);  fma2(a1[0], s1a, E0);
        fma2(e1[1], p1a, E1);  fma2(a1[1], s1a, E1);
        fma2(e1[2], p1a, E2);  fma2(a1[2], s1a, E2);
        fma2(e1[3], p1a, E3);  fma2(a1[3], s1a, E3);
        fma2(e1[4], p1a, E4);  fma2(a1[4], s1a, E4);
        fma2(f1e[0], p1b, E1); fma2(f1a[0], s1b, E1);
        fma2(f1e[1], p1b, E2); fma2(f1a[1], s1b, E2);
        fma2(f1e[2], p1b, E3); fma2(f1a[2], s1b, E3);
        fma2(f1e[3], p1b, E4); fma2(f1a[3], s1b, E4);
        fma2(f1e[4], p1b, E5); fma2(f1a[4], s1b, E5);

        V0 = nV0; V1 = nV1; V2 = nV2;
        sp = spn;
    }

    const unsigned sb = __float_as_uint(1.0f / (float)C_);
    const ull scale2 = (ull)sb | ((ull)sb << 32);

    if (g <= 8) {   // set 0: channel g*9+dx at row h0
        float* od = out + (((size_t)(b * 81 + g * 9)) * H_ + h0) * W_ + w0;
#pragma unroll
        for (int m = 0; m < 5; m++) {
            ull va = e0[m];  mul2(va, scale2);
            ull vb = f0e[m]; mul2(vb, scale2);
            ulonglong2 pk; pk.x = va; pk.y = vb;
            *reinterpret_cast<ulonglong2*>(od + (size_t)(2 * m) * HW_) = pk;
        }
#pragma unroll
        for (int m = 0; m < 4; m++) {
            ull va = pack_hl(a0[m], a0[m + 1]); mul2(va, scale2);
            ull vb = pack_hl(f0a[m], f0a[m + 1]); mul2(vb, scale2);
            ulonglong2 pk; pk.x = va; pk.y = vb;
            *reinterpret_cast<ulonglong2*>(od + (size_t)(2 * m + 1) * HW_) = pk;
        }
    }
    if (g >= 1) {   // set 1: channel (g-1)*9+dx at row h0+1
        float* od = out + (((size_t)(b * 81 + (g - 1) * 9)) * H_ + (h0 + 1)) * W_ + w0;
#pragma unroll
        for (int m = 0; m < 5; m++) {
            ull va = e1[m];  mul2(va, scale2);
            ull vb = f1e[m]; mul2(vb, scale2);
            ulonglong2 pk; pk.x = va; pk.y = vb;
            *reinterpret_cast<ulonglong2*>(od + (size_t)(2 * m) * HW_) = pk;
        }
#pragma unroll
        for (int m = 0; m < 4; m++) {
            ull va = pack_hl(a1[m], a1[m + 1]); mul2(va, scale2);
            ull vb = pack_hl(f1a[m], f1a[m + 1]); mul2(vb, scale2);
            ulonglong2 pk; pk.x = va; pk.y = vb;
            *reinterpret_cast<ulonglong2*>(od + (size_t)(2 * m + 1) * HW_) = pk;
        }
    }
}

extern "C" void kernel_launch(void* const* d_in, const int* in_sizes, int n_in,
                              void* d_out, int out_size) {
    const float* first  = (const float*)d_in[0];
    const float* second = (const float*)d_in[1];
    float* out = (float*)d_out;

    const int pad_elems = B_ * C_ * HP_ * (WP_ / 4);
    pad_kernel<<<(pad_elems + 255) / 256, 256>>>(second);

    dim3 grid(H_ / 2, 2, B_);   // (56 h-pairs, 2 W-halves, 8 batches)
    corr81_kernel<<<grid, 240>>>(first, out);
}

// round 16
// speedup vs baseline: 1.4736x; 1.3242x over previous
#include <cuda_runtime.h>
#include <cstdint>

// PWC-Net correlation, B=8, C=128, H=112, W=192, 81 disps (dy,dx in [-4,4]).
// Round 16: NO pad buffer/kernel. Direct reads of `second` with three
// per-thread quad pointers; out-of-image quads are replaced by a pointer to a
// static zero quad with stride 0 -> exact padded semantics, no masks, no OOB.
// R9 compute core (h-pair register blocking, distance-1 V prefetch); strides
// added unconditionally (last channel peeled), F1 via +768B immediate.

#define B_ 8
#define C_ 128
#define H_ 112
#define W_ 192
#define HW_ (H_ * W_)

typedef unsigned long long ull;

__device__ __align__(16) float g_zero[4];   // zero-initialized

__device__ __forceinline__ void fma2(ull& acc, ull a, ull b) {
    asm("fma.rn.f32x2 %0, %1, %2, %0;" : "+l"(acc) : "l"(a), "l"(b));
}
__device__ __forceinline__ void mul2(ull& v, ull s) {
    asm("mul.rn.f32x2 %0, %0, %1;" : "+l"(v) : "l"(s));
}
__device__ __forceinline__ ull pack_hl(ull a, ull b) {   // (a.hi, b.lo)
    return (a >> 32) | (b << 32);
}
__device__ __forceinline__ ull swap2(ull a) {            // (a.hi, a.lo)
    return (a >> 32) | (a << 32);
}
__device__ __forceinline__ ull lo_(float x, float y) {
    return (ull)__float_as_uint(x) | ((ull)__float_as_uint(y) << 32);
}

// FMA block for one channel: V0..V2 (12 second cols), F0/F1 (first rows h0,h0+1)
#define FMA_BLOCK(V0_, V1_, V2_, F0_, F1_) do {                              \
    const ull E0 = lo_(V0_.x, V0_.y), E1 = lo_(V0_.z, V0_.w);                \
    const ull E2 = lo_(V1_.x, V1_.y), E3 = lo_(V1_.z, V1_.w);                \
    const ull E4 = lo_(V2_.x, V2_.y), E5 = lo_(V2_.z, V2_.w);                \
    const ull p0a = lo_(F0_.x, F0_.y), p0b = lo_(F0_.z, F0_.w);              \
    const ull s0a = swap2(p0a),        s0b = swap2(p0b);                     \
    const ull p1a = lo_(F1_.x, F1_.y), p1b = lo_(F1_.z, F1_.w);              \
    const ull s1a = swap2(p1a),        s1b = swap2(p1b);                     \
    fma2(e0[0], p0a, E0);  fma2(a0[0], s0a, E0);                             \
    fma2(e0[1], p0a, E1);  fma2(a0[1], s0a, E1);                             \
    fma2(e0[2], p0a, E2);  fma2(a0[2], s0a, E2);                             \
    fma2(e0[3], p0a, E3);  fma2(a0[3], s0a, E3);                             \
    fma2(e0[4], p0a, E4);  fma2(a0[4], s0a, E4);                             \
    fma2(f0e[0], p0b, E1); fma2(f0a[0], s0b, E1);                            \
    fma2(f0e[1], p0b, E2); fma2(f0a[1], s0b, E2);                            \
    fma2(f0e[2], p0b, E3); fma2(f0a[2], s0b, E3);                            \
    fma2(f0e[3], p0b, E4); fma2(f0a[3], s0b, E4);                            \
    fma2(f0e[4], p0b, E5); fma2(f0a[4], s0b, E5);                            \
    fma2(e1[0], p1a, E0);  fma2(a1[0], s1a, E0);                             \
    fma2(e1[1], p1a, E1);  fma2(a1[1], s1a, E1);                             \
    fma2(e1[2], p1a, E2);  fma2(a1[2], s1a, E2);                             \
    fma2(e1[3], p1a, E3);  fma2(a1[3], s1a, E3);                             \
    fma2(e1[4], p1a, E4);  fma2(a1[4], s1a, E4);                             \
    fma2(f1e[0], p1b, E1); fma2(f1a[0], s1b, E1);                            \
    fma2(f1e[1], p1b, E2); fma2(f1a[1], s1b, E2);                            \
    fma2(f1e[2], p1b, E3); fma2(f1a[2], s1b, E3);                            \
    fma2(f1e[3], p1b, E4); fma2(f1a[3], s1b, E4);                            \
    fma2(f1e[4], p1b, E5); fma2(f1a[4], s1b, E5);                            \
} while (0)

__global__ __launch_bounds__(480, 1)
void corr81_kernel(const float* __restrict__ first,
                   const float* __restrict__ second,
                   float* __restrict__ out) {
    const int h0  = 2 * blockIdx.x;    // output rows h0, h0+1
    const int b   = blockIdx.y;
    const int tid = threadIdx.x;       // 0..479
    const int pq  = tid % 48;
    const int g   = tid / 48;          // 0..9: second row = h0 + g - 4
    const int w0  = 4 * pq;

    // set 0: output row h0, dy_pad = g      (store if g<=8)
    // set 1: output row h0+1, dy_pad = g-1  (store if g>=1)
    ull e0[5], a0[5], f0e[5], f0a[5];
    ull e1[5], a1[5], f1e[5], f1a[5];
#pragma unroll
    for (int m = 0; m < 5; m++) {
        e0[m]=0; a0[m]=0; f0e[m]=0; f0a[m]=0;
        e1[m]=0; a1[m]=0; f1e[m]=0; f1a[m]=0;
    }

    // V pointers: quads at cols w0-4 / w0 / w0+4 of second row y = h0+g-4.
    // Out-of-image quads -> static zero quad with stride 0 (exact pad semantics).
    const int  y   = h0 + g - 4;
    const bool yok = (y >= 0) && (y < H_);
    const float* rowb = second + ((size_t)(b * C_) * H_ + (yok ? y : 0)) * W_;
    const float4* zq  = reinterpret_cast<const float4*>(g_zero);

    const bool ok0 = yok && (w0 >= 4);
    const bool ok2 = yok && (w0 <= 184);
    const float4* p0 = ok0 ? reinterpret_cast<const float4*>(rowb + w0 - 4) : zq;
    const float4* p1 = yok ? reinterpret_cast<const float4*>(rowb + w0)     : zq;
    const float4* p2 = ok2 ? reinterpret_cast<const float4*>(rowb + w0 + 4) : zq;
    const int s0 = ok0 ? (int)(HW_ * sizeof(float)) : 0;   // byte strides
    const int s1 = yok ? (int)(HW_ * sizeof(float)) : 0;
    const int s2 = ok2 ? (int)(HW_ * sizeof(float)) : 0;

    const float4* fp = reinterpret_cast<const float4*>(
        first + ((size_t)(b * C_) * H_ + h0) * W_ + w0);

    // prologue: V for channel 0
    float4 V0 = *p0, V1 = *p1, V2 = *p2;

    for (int c = 0; c < C_ - 1; c++) {
        // unconditional advance (no select); loads channel c+1's V
        p0 = reinterpret_cast<const float4*>(reinterpret_cast<const char*>(p0) + s0);
        p1 = reinterpret_cast<const float4*>(reinterpret_cast<const char*>(p1) + s1);
        p2 = reinterpret_cast<const float4*>(reinterpret_cast<const char*>(p2) + s2);
        const float4 nV0 = *p0;
        const float4 nV1 = *p1;
        const float4 nV2 = *p2;

        const float4 F0 = fp[0];
        const float4 F1 = fp[W_ / 4];      // row h0+1: +768B immediate
        fp += HW_ / 4;

        FMA_BLOCK(V0, V1, V2, F0, F1);

        V0 = nV0; V1 = nV1; V2 = nV2;
    }
    {   // peeled last channel (c = 127): no prefetch
        const float4 F0 = fp[0];
        const float4 F1 = fp[W_ / 4];
        FMA_BLOCK(V0, V1, V2, F0, F1);
    }

    const unsigned sb = __float_as_uint(1.0f / (float)C_);
    const ull scale2 = (ull)sb | ((ull)sb << 32);

    if (g <= 8) {   // set 0: channel g*9+dx at row h0
        float* od = out + (((size_t)(b * 81 + g * 9)) * H_ + h0) * W_ + w0;
#pragma unroll
        for (int m = 0; m < 5; m++) {
            ull va = e0[m];  mul2(va, scale2);
            ull vb = f0e[m]; mul2(vb, scale2);
            ulonglong2 pk; pk.x = va; pk.y = vb;
            *reinterpret_cast<ulonglong2*>(od + (size_t)(2 * m) * HW_) = pk;
        }
#pragma unroll
        for (int m = 0; m < 4; m++) {
            ull va = pack_hl(a0[m], a0[m + 1]); mul2(va, scale2);
            ull vb = pack_hl(f0a[m], f0a[m + 1]); mul2(vb, scale2);
            ulonglong2 pk; pk.x = va; pk.y = vb;
            *reinterpret_cast<ulonglong2*>(od + (size_t)(2 * m + 1) * HW_) = pk;
        }
    }
    if (g >= 1) {   // set 1: channel (g-1)*9+dx at row h0+1
        float* od = out + (((size_t)(b * 81 + (g - 1) * 9)) * H_ + (h0 + 1)) * W_ + w0;
#pragma unroll
        for (int m = 0; m < 5; m++) {
            ull va = e1[m];  mul2(va, scale2);
            ull vb = f1e[m]; mul2(vb, scale2);
            ulonglong2 pk; pk.x = va; pk.y = vb;
            *reinterpret_cast<ulonglong2*>(od + (size_t)(2 * m) * HW_) = pk;
        }
#pragma unroll
        for (int m = 0; m < 4; m++) {
            ull va = pack_hl(a1[m], a1[m + 1]); mul2(va, scale2);
            ull vb = pack_hl(f1a[m], f1a[m + 1]); mul2(vb, scale2);
            ulonglong2 pk; pk.x = va; pk.y = vb;
            *reinterpret_cast<ulonglong2*>(od + (size_t)(2 * m + 1) * HW_) = pk;
        }
    }
}

extern "C" void kernel_launch(void* const* d_in, const int* in_sizes, int n_in,
                              void* d_out, int out_size) {
    const float* first  = (const float*)d_in[0];
    const float* second = (const float*)d_in[1];
    float* out = (float*)d_out;

    dim3 grid(H_ / 2, B_);   // (56 h-pairs, 8 batches)
    corr81_kernel<<<grid, 480>>>(first, second, out);
}